// round 7
// baseline (speedup 1.0000x reference)
#include <cuda_runtime.h>

// ---------------------------------------------------------------------------
// MOE_DISTRIBUTE_CASCADE_GRAPH
//   inv[i]   = stable counting-sort rank of expert_ids.flat[i]   (N = B*K)
//   out[b,h] = sum_k scales[b,k] * G[inv[b*K+k], h]
//   output   = (out, out) concatenated (2*B*H floats)
//
// Rank = chip-wide 3-phase counting sort (beats the 1-SM fused version):
//   K1: per-chunk (256 ids) local stable ranks + hist[e][chunk]   (128 blocks)
//   K2: per-expert prefix over chunks + expert-base scan          (1 block)
//   K3: g_inv[i] += chunk_prefix[e][c] + expert_base[e]           (128 blocks)
// ---------------------------------------------------------------------------

#define NBINS   256        // max experts supported (dataset uses 64)
#define NCHUNK  256        // max chunks (chunk = 256 ids -> N <= 65536)
#define CHSZ    256        // ids per chunk / threads per K1,K3 block
#define MAXN    (NCHUNK * CHSZ)

__device__ int g_inv[MAXN];
__device__ int g_hist[NBINS * NCHUNK];   // [expert][chunk], expert-major
__device__ int g_base[NBINS * NCHUNK];   // exclusive prefix over chunks
__device__ int g_ebase[NBINS];           // exclusive prefix over experts

// --- K1: per-chunk local stable ranks + histogram ----------------------------
// 256 threads = 8 warps, one id per lane -> exactly ONE match step per warp.
__global__ void __launch_bounds__(CHSZ, 4)
rank_local_kernel(const int* __restrict__ ids, int n) {
    __shared__ int cnt[8 * NBINS];
    const unsigned FULL = 0xffffffffu;
    const int blk  = blockIdx.x;
    const int tid  = threadIdx.x;
    const int w    = tid >> 5;
    const int lane = tid & 31;
    const int i    = blk * CHSZ + tid;

    for (int j = tid; j < 8 * NBINS; j += CHSZ) cnt[j] = 0;
    __syncthreads();

    const bool valid = (i < n);
    const int  key   = valid ? ids[i] : (NBINS + lane);   // singleton if invalid
    const unsigned mask = __match_any_sync(FULL, key);
    const int lower  = __popc(mask & ((1u << lane) - 1u));
    const int leader = __ffs(mask) - 1;
    if (valid && lane == leader)
        cnt[w * NBINS + key] = __popc(mask);
    __syncthreads();

    // per-expert exclusive scan over the 8 warp rows; row totals -> g_hist
    if (tid < NBINS) {
        int run = 0;
        #pragma unroll
        for (int ww = 0; ww < 8; ww++) {
            const int h = cnt[ww * NBINS + tid];
            cnt[ww * NBINS + tid] = run;
            run += h;
        }
        g_hist[tid * NCHUNK + blk] = run;    // expert-major for K2
    }
    __syncthreads();

    if (valid) g_inv[i] = lower + cnt[w * NBINS + key];   // chunk-local rank
}

// --- K2: per-expert prefix over chunks + expert-base scan --------------------
// Thread e scans its contiguous 4B*nchunk row (counted loop -> batched loads).
__global__ void __launch_bounds__(NBINS, 1)
scan_kernel(int nchunk) {
    __shared__ int totals[NBINS];
    const int e = threadIdx.x;

    int run = 0;
    #pragma unroll 8
    for (int c = 0; c < nchunk; c++) {
        const int h = g_hist[e * NCHUNK + c];
        g_base[e * NCHUNK + c] = run;
        run += h;
    }
    totals[e] = run;
    __syncthreads();

    // inclusive Hillis-Steele over expert totals
    #pragma unroll
    for (int d = 1; d < NBINS; d <<= 1) {
        const int v = (e >= d) ? totals[e - d] : 0;
        __syncthreads();
        totals[e] += v;
        __syncthreads();
    }
    g_ebase[e] = (e == 0) ? 0 : totals[e - 1];
}

// --- K3: add global bases (fully parallel, L2-warm) ---------------------------
__global__ void __launch_bounds__(CHSZ, 4)
add_base_kernel(const int* __restrict__ ids, int n) {
    const int i = blockIdx.x * CHSZ + threadIdx.x;
    if (i < n) {
        const int e = ids[i];
        g_inv[i] += g_base[e * NCHUNK + blockIdx.x] + g_ebase[e];
    }
}

// --- Combine: gather-reduce, HBM streaming roofline (R6-measured best) -------
// 256 threads, 4 blocks/SM, two float4 columns per thread; GUARD=false is the
// exact-fit path (H4 % 512 == 0).
template <int K, bool GUARD>
__global__ void __launch_bounds__(256, 4)
combine_kernel(const float* __restrict__ G,
               const float* __restrict__ scales,
               float* __restrict__ out,
               int B, int H4, int dup) {
    const int b  = blockIdx.y;
    const int h0 = blockIdx.x * 512 + threadIdx.x;
    const int h1 = h0 + 256;
    __shared__ int   rows[K];
    __shared__ float sc[K];
    if (threadIdx.x < K) {
        rows[threadIdx.x] = g_inv[b * K + threadIdx.x];
        sc[threadIdx.x]   = scales[b * K + threadIdx.x];
    }
    __syncthreads();

    const float4* __restrict__ Gv = reinterpret_cast<const float4*>(G);
    float4* __restrict__ ov = reinterpret_cast<float4*>(out);

    const bool v0 = GUARD ? (h0 < H4) : true;
    const bool v1 = GUARD ? (h1 < H4) : true;
    float4 acc0 = make_float4(0.f, 0.f, 0.f, 0.f);
    float4 acc1 = make_float4(0.f, 0.f, 0.f, 0.f);
    #pragma unroll
    for (int k = 0; k < K; k++) {
        const float  s = sc[k];
        const size_t rb = (size_t)rows[k] * H4;
        if (v0) {
            const float4 a = __ldg(&Gv[rb + h0]);
            acc0.x = fmaf(s, a.x, acc0.x);
            acc0.y = fmaf(s, a.y, acc0.y);
            acc0.z = fmaf(s, a.z, acc0.z);
            acc0.w = fmaf(s, a.w, acc0.w);
        }
        if (v1) {
            const float4 c = __ldg(&Gv[rb + h1]);
            acc1.x = fmaf(s, c.x, acc1.x);
            acc1.y = fmaf(s, c.y, acc1.y);
            acc1.z = fmaf(s, c.z, acc1.z);
            acc1.w = fmaf(s, c.w, acc1.w);
        }
    }
    const size_t ob = (size_t)b * H4;
    if (v0) ov[ob + h0] = acc0;
    if (v1) ov[ob + h1] = acc1;
    if (dup) {
        const size_t od = (size_t)B * H4 + ob;
        if (v0) ov[od + h0] = acc0;
        if (v1) ov[od + h1] = acc1;
    }
}

// generic-K fallback
__global__ void __launch_bounds__(256, 4)
combine_kernel_gen(const float* __restrict__ G,
                   const float* __restrict__ scales,
                   float* __restrict__ out,
                   int B, int K, int H4, int dup) {
    const int b = blockIdx.y;
    const int h = blockIdx.x * 256 + threadIdx.x;
    __shared__ int   rows[32];
    __shared__ float sc[32];
    if (threadIdx.x < (unsigned)K) {
        rows[threadIdx.x] = g_inv[b * K + threadIdx.x];
        sc[threadIdx.x]   = scales[b * K + threadIdx.x];
    }
    __syncthreads();
    if (h >= H4) return;

    const float4* __restrict__ Gv = reinterpret_cast<const float4*>(G);
    float4* __restrict__ ov = reinterpret_cast<float4*>(out);

    float4 acc = make_float4(0.f, 0.f, 0.f, 0.f);
    for (int k = 0; k < K; k++) {
        const float  s = sc[k];
        const float4 v = __ldg(&Gv[(size_t)rows[k] * H4 + h]);
        acc.x = fmaf(s, v.x, acc.x);
        acc.y = fmaf(s, v.y, acc.y);
        acc.z = fmaf(s, v.z, acc.z);
        acc.w = fmaf(s, v.w, acc.w);
    }
    const size_t o = (size_t)b * H4 + h;
    ov[o] = acc;
    if (dup) ov[(size_t)B * H4 + o] = acc;
}

// ---------------------------------------------------------------------------
extern "C" void kernel_launch(void* const* d_in, const int* in_sizes, int n_in,
                              void* d_out, int out_size) {
    // metadata order: x[B,H] f32, expert_ids[B,K] i32, expert_scales[B,K] f32,
    //                 golden_expand_x[B*K,H] f32, moe_expert_num i32
    const int*   ids    = (const int*)  d_in[1];
    const float* scales = (const float*)d_in[2];
    const float* G      = (const float*)d_in[3];
    float*       out    = (float*)d_out;

    const int N  = in_sizes[1];                     // B*K = 32768
    const long long GH = (long long)in_sizes[3];    // N*H
    const int H  = (int)(GH / N);                   // 4096
    const int B  = in_sizes[0] / H;                 // 4096
    const int K  = N / B;                           // 8
    const int H4 = H >> 2;
    const int dup = (out_size >= 2 * B * H) ? 1 : 0;
    const int nchunk = (N + CHSZ - 1) / CHSZ;       // 128

    rank_local_kernel<<<nchunk, CHSZ>>>(ids, N);
    scan_kernel<<<1, NBINS>>>(nchunk);
    add_base_kernel<<<nchunk, CHSZ>>>(ids, N);

    if (K == 8) {
        const int cpb = (H4 + 511) / 512;           // 512 float4 cols per block
        dim3 grid(cpb, B);
        if ((H4 & 511) == 0)
            combine_kernel<8, false><<<grid, 256>>>(G, scales, out, B, H4, dup);
        else
            combine_kernel<8, true><<<grid, 256>>>(G, scales, out, B, H4, dup);
    } else {
        const int cpb = (H4 + 255) / 256;
        dim3 grid(cpb, B);
        combine_kernel_gen<<<grid, 256>>>(G, scales, out, B, K, H4, dup);
    }
}